// round 6
// baseline (speedup 1.0000x reference)
#include <cuda_runtime.h>
#include <cuda_bf16.h>
#include <cstddef>

// Problem constants
#define TT 4
#define BB 16
#define CIN 3
#define HIMG 64
#define WIMG 64
#define NN 6
#define COUT 128
#define HP 32
#define WP 32

// Persistent state (device globals; zeroed at start of every launch)
__device__ float g_v0[BB * COUT * HIMG * WIMG];
__device__ float g_vn[5 * BB * COUT * HP * WP];
__device__ float g_traces[BB * NN * COUT];
__device__ float g_out0[BB * COUT * HP * WP];
__device__ float g_mean0[BB * COUT];
__device__ float g_feat0[BB * COUT];
__device__ float g_msp[5 * BB * COUT];
__device__ float g_c[BB * NN];

__device__ __forceinline__ float sigf(float x) { return 1.f / (1.f + expf(-x)); }

// packed fp32x2 helpers (sm_103a FFMA2 path)
__device__ __forceinline__ unsigned long long pk2(float a, float b) {
    unsigned long long r;
    asm("mov.b64 %0, {%1, %2};" : "=l"(r) : "f"(a), "f"(b));
    return r;
}
__device__ __forceinline__ void upk2(unsigned long long p, float& a, float& b) {
    asm("mov.b64 {%0, %1}, %2;" : "=f"(a), "=f"(b) : "l"(p));
}
__device__ __forceinline__ unsigned long long ffma2(unsigned long long a,
                                                    unsigned long long b,
                                                    unsigned long long c) {
    unsigned long long d;
    asm("fma.rn.f32x2 %0, %1, %2, %3;" : "=l"(d) : "l"(a), "l"(b), "l"(c));
    return d;
}

// ---------------------------------------------------------------------------
// K0: zero state
// ---------------------------------------------------------------------------
__global__ void k0_zero() {
    const size_t n0 = (size_t)BB * COUT * HIMG * WIMG;
    const size_t n1 = (size_t)5 * BB * COUT * HP * WP;
    const size_t n2 = (size_t)BB * NN * COUT;
    const size_t tot = n0 + n1 + n2;
    for (size_t i = (size_t)blockIdx.x * blockDim.x + threadIdx.x; i < tot;
         i += (size_t)gridDim.x * blockDim.x) {
        if (i < n0) g_v0[i] = 0.f;
        else if (i < n0 + n1) g_vn[i - n0] = 0.f;
        else g_traces[i - n0 - n1] = 0.f;
    }
}

// ---------------------------------------------------------------------------
// K1: conv0(3->128, 3x3, SAME) + BN + PLIF + spike + 2x2 avgpool
// ---------------------------------------------------------------------------
__global__ void k1_conv0(const float* __restrict__ x, const float* __restrict__ w0,
                         const float* __restrict__ bg, const float* __restrict__ bb,
                         const float* __restrict__ bm, const float* __restrict__ bv,
                         const float* __restrict__ plw, const float* __restrict__ outw,
                         float* __restrict__ dout, int t) {
    extern __shared__ float tile[];   // [3][66][66]
    __shared__ float ws[27];
    __shared__ float red[256];
    int b = blockIdx.x, c = blockIdx.y, tid = threadIdx.x;

    const float* xb = x + (((size_t)t * BB + b) * CIN) * (HIMG * WIMG);
    for (int idx = tid; idx < 3 * 66 * 66; idx += 256) {
        int ic = idx / 4356, rem = idx % 4356;
        int r = rem / 66, cc = rem % 66;
        int y = r - 1, xx = cc - 1;
        float v = 0.f;
        if ((unsigned)y < 64u && (unsigned)xx < 64u) v = xb[ic * 4096 + y * 64 + xx];
        tile[idx] = v;
    }
    if (tid < 27) ws[tid] = w0[c * 27 + tid];
    __syncthreads();

    float scale = bg[c] / sqrtf(bv[c] + 1e-5f);
    float shift = bb[c] - bm[c] * scale;
    float sg = sigf(plw[0]);
    float wsig0 = sigf(outw[0]);

    float* v0p = g_v0 + ((size_t)b * COUT + c) * (HIMG * WIMG);
    float* o0p = g_out0 + ((size_t)b * COUT + c) * (HP * WP);
    float* dop = dout + ((((size_t)t * BB + b) * COUT + c)) * (HP * WP);

    float lsum = 0.f;
    for (int k = 0; k < 4; k++) {
        int q = tid + k * 256;
        int ph = q >> 5, pw = q & 31;
        float psum = 0.f;
        #pragma unroll
        for (int dy = 0; dy < 2; dy++) {
            #pragma unroll
            for (int dx = 0; dx < 2; dx++) {
                int yy = 2 * ph + dy, xx = 2 * pw + dx;
                float acc = 0.f;
                #pragma unroll
                for (int ic = 0; ic < 3; ic++) {
                    const float* tp = tile + ic * 4356 + yy * 66 + xx;
                    const float* wp = ws + ic * 9;
                    #pragma unroll
                    for (int ky = 0; ky < 3; ky++)
                        #pragma unroll
                        for (int kx = 0; kx < 3; kx++)
                            acc += tp[ky * 66 + kx] * wp[ky * 3 + kx];
                }
                float bnv = acc * scale + shift;
                float vold = v0p[yy * 64 + xx];
                float v = vold + (bnv - vold) * sg;
                float sp = (v >= 1.f) ? 1.f : 0.f;
                v0p[yy * 64 + xx] = (v >= 1.f) ? 0.f : v;
                psum += sp;
            }
        }
        float o = psum * 0.25f;
        o0p[q] = o;
        dop[q] = wsig0 * o;
        lsum += o;
    }
    red[tid] = lsum;
    __syncthreads();
    for (int off = 128; off; off >>= 1) {
        if (tid < off) red[tid] += red[tid + off];
        __syncthreads();
    }
    if (tid == 0) g_mean0[b * COUT + c] = red[0] * (1.f / 1024.f);
}

// ---------------------------------------------------------------------------
// K2: per-batch tiny graph work
// ---------------------------------------------------------------------------
__global__ void k2_graph(const float* __restrict__ ftw, const float* __restrict__ ftb,
                         const float* __restrict__ gatW, const float* __restrict__ gata) {
    int b = blockIdx.x, tid = threadIdx.x;
    __shared__ float tr[NN * COUT];
    __shared__ float m0[COUT];
    __shared__ float hp[NN * COUT];
    __shared__ float e1[NN * 4], e2[NN * 4];
    __shared__ float attn[36], Sm[36], adj[36], opm[36], dis[NN];

    m0[tid] = g_mean0[b * COUT + tid];
    for (int n = 0; n < NN; n++) tr[n * COUT + tid] = g_traces[((size_t)b * NN + n) * COUT + tid];
    __syncthreads();

    float f = ftb[tid];
    for (int d = 0; d < COUT; d++) f += m0[d] * ftw[tid * COUT + d];
    f = fmaxf(f, 0.f);
    g_feat0[b * COUT + tid] = f;
    float t0 = 0.6f * tr[tid] + 0.4f * f;
    tr[tid] = t0;
    g_traces[(size_t)b * NN * COUT + tid] = t0;
    __syncthreads();

    for (int n = 0; n < NN; n++) {
        float s = 0.f;
        for (int k = 0; k < COUT; k++) s += tr[n * COUT + k] * gatW[tid * COUT + k];
        hp[n * COUT + tid] = s;
    }
    __syncthreads();

    if (tid < NN * 4) {
        int n = tid >> 2, h = tid & 3;
        float s1 = 0.f, s2 = 0.f;
        for (int d = 0; d < 32; d++) {
            float hv = hp[n * COUT + h * 32 + d];
            s1 += hv * gata[h * 64 + d];
            s2 += hv * gata[h * 64 + 32 + d];
        }
        e1[tid] = s1;
        e2[tid] = s2;
    }
    __syncthreads();

    if (tid < 36) {
        int i = tid / 6, j = tid % 6;
        float s = 0.f;
        for (int h = 0; h < 4; h++) {
            float x1 = e1[i * 4 + h] + e2[j * 4 + h];
            float x2 = e1[j * 4 + h] + e2[i * 4 + h];
            x1 = x1 > 0.f ? x1 : 0.2f * x1;
            x2 = x2 > 0.f ? x2 : 0.2f * x2;
            s += 0.5f * (x1 + x2);
        }
        attn[tid] = s * 0.25f;
    }
    __syncthreads();

    if (tid < NN) {
        int i = tid;
        float mx = -1e30f;
        for (int j = 0; j < 6; j++) mx = fmaxf(mx, attn[i * 6 + j] * 100.f);
        float ex[6], sum = 0.f;
        for (int j = 0; j < 6; j++) { ex[j] = expf(attn[i * 6 + j] * 100.f - mx); sum += ex[j]; }
        for (int j = 0; j < 6; j++) Sm[i * 6 + j] = ex[j] / sum;
    }
    __syncthreads();

    if (tid < NN) {
        int i = tid;
        float a[6];
        for (int j = 0; j < 6; j++) a[j] = Sm[i * 6 + j];
        float kth = 0.f;
        for (int r = 0; r < 3; r++) {
            int bi = 0; float bvv = -1e30f;
            for (int j = 0; j < 6; j++) if (a[j] > bvv) { bvv = a[j]; bi = j; }
            kth = bvv; a[bi] = -1e30f;
        }
        for (int j = 0; j < 6; j++) Sm[i * 6 + j] = (Sm[i * 6 + j] >= kth) ? Sm[i * 6 + j] : 0.f;
    }
    __syncthreads();

    if (tid < 36) { int i = tid / 6, j = tid % 6; adj[tid] = 0.5f * (Sm[i * 6 + j] + Sm[j * 6 + i]); }
    __syncthreads();
    if (tid < NN) {
        float s = 0.f;
        for (int j = 0; j < 6; j++) s += adj[tid * 6 + j];
        dis[tid] = 1.f / sqrtf(s + 1e-6f);
    }
    __syncthreads();
    if (tid < 36) { int i = tid / 6, j = tid % 6; opm[tid] = dis[i] * adj[tid] * dis[j]; }
    __syncthreads();
    if (tid < NN) {
        float s = 0.f;
        for (int j = 0; j < 6; j++) s += opm[tid * 6 + j] * opm[j * 6 + 0];
        g_c[b * NN + tid] = s;
    }
}

// ---------------------------------------------------------------------------
// K3: batched node conv via FFMA2 with OVERLAPPING-PAIR smem staging.
// pair_s[ic][r][j] = (in_pad[j], in_pad[j+1])  -> every conv tap is an
// aligned LDS.64; no register packing in the hot loop.
// grid (B, COUT/2); 256 threads; half-block per c_out.
// Thread map: row = t2&31, x0 = (t2>>5)*8  (warp = 32 rows, one col group;
// odd float2 row-stride 35 => conflict-free 64-bit LDS per phase).
// 4 input channels per chunk, 32 chunks.
// ---------------------------------------------------------------------------
#define P_STRIDE 35              // row stride in float2 units (odd)
#define P_IC (34 * P_STRIDE)     // 1190 pairs per ic plane

__global__ void __launch_bounds__(256) k3_nodeconv(
    const float* __restrict__ convw, const float* __restrict__ bg,
    const float* __restrict__ bb, const float* __restrict__ bm,
    const float* __restrict__ bv, const float* __restrict__ plw,
    const float* __restrict__ outw, float* __restrict__ dout, int t) {
    __shared__ unsigned long long pair_s[4 * P_IC];  // 38,080 B
    __shared__ unsigned long long w2_s[360];         // 2,880 B (2co x 5i x 4ic x 9, dup pairs)
    int b = blockIdx.x, cp = blockIdx.y, tid = threadIdx.x;
    int half = tid >> 7, t2 = tid & 127;
    int co = cp * 2 + half;
    int row = t2 & 31, x0 = (t2 >> 5) * 8;

    unsigned long long acc2[5][4];
    #pragma unroll
    for (int i = 0; i < 5; i++)
        #pragma unroll
        for (int j = 0; j < 4; j++) acc2[i][j] = 0ull;

    const float* o0b = g_out0 + (size_t)b * COUT * (HP * WP);
    const int wbase = half * 180;

    for (int kc = 0; kc < 32; kc++) {
        __syncthreads();
        // Stage overlapping pairs: 4 ic x 34 rows x 34 pair-cols
        for (int idx = tid; idx < 4 * 34 * 34; idx += 256) {
            int ic = idx / 1156, rem = idx % 1156;
            int r = rem / 34, j = rem % 34;
            int y = r - 1;
            const float* src = o0b + (size_t)(kc * 4 + ic) * 1024 + y * 32;
            bool yok = (unsigned)y < 32u;
            float v0 = (yok && (unsigned)(j - 1) < 32u) ? src[j - 1] : 0.f;
            float v1 = (yok && (unsigned)j < 32u) ? src[j] : 0.f;
            pair_s[ic * P_IC + r * P_STRIDE + j] = pk2(v0, v1);
        }
        // Stage weights as duplicated pairs
        for (int idx = tid; idx < 360; idx += 256) {
            int h2 = idx / 180, r = idx % 180;
            int i = r / 36, r2 = r % 36, ic = r2 / 9, k = r2 % 9;
            int col = cp * 2 + h2;
            float w = convw[(((size_t)i * COUT + col) * COUT + kc * 4 + ic) * 9 + k];
            w2_s[idx] = pk2(w, w);
        }
        __syncthreads();
        #pragma unroll
        for (int ic = 0; ic < 4; ic++) {
            const unsigned long long* ip = pair_s + ic * P_IC + row * P_STRIDE + x0;
            #pragma unroll
            for (int ky = 0; ky < 3; ky++) {
                const unsigned long long* rp = ip + ky * P_STRIDE;
                unsigned long long P[9];
                #pragma unroll
                for (int k = 0; k < 9; k++) P[k] = rp[k];
                #pragma unroll
                for (int i = 0; i < 5; i++) {
                    const unsigned long long* wp = w2_s + wbase + i * 36 + ic * 9 + ky * 3;
                    unsigned long long w0 = wp[0], w1 = wp[1], w2v = wp[2];
                    #pragma unroll
                    for (int j = 0; j < 4; j++) {
                        acc2[i][j] = ffma2(P[2 * j], w0, acc2[i][j]);
                        acc2[i][j] = ffma2(P[2 * j + 1], w1, acc2[i][j]);
                        acc2[i][j] = ffma2(P[2 * j + 2], w2v, acc2[i][j]);
                    }
                }
            }
        }
    }

    // Epilogue: scale by c, BN, PLIF, spike, state write, output accumulate
    float outacc[8];
    #pragma unroll
    for (int p = 0; p < 8; p++) outacc[p] = 0.f;
    float spsum[5];
    int pxbase = row * 32 + x0;

    #pragma unroll
    for (int i = 0; i < 5; i++) {
        float ci = g_c[b * NN + i + 1];
        float sc = bg[i * COUT + co] / sqrtf(bv[i * COUT + co] + 1e-5f);
        float sh = bb[i * COUT + co] - bm[i * COUT + co] * sc;
        float sg = sigf(plw[i + 1]);
        float wsg = sigf(outw[i + 1]);
        float csc = ci * sc;
        float* vp = g_vn + ((((size_t)i * BB + b) * COUT + co) << 10);
        float ss = 0.f;
        #pragma unroll
        for (int j = 0; j < 4; j++) {
            float a0, a1;
            upk2(acc2[i][j], a0, a1);
            float av[2] = {a0, a1};
            #pragma unroll
            for (int u = 0; u < 2; u++) {
                int p = 2 * j + u;
                float y = av[u] * csc + sh;
                float vold = vp[pxbase + p];
                float v = vold + (y - vold) * sg;
                float sp = (v >= 1.f) ? 1.f : 0.f;
                vp[pxbase + p] = (v >= 1.f) ? 0.f : v;
                outacc[p] += wsg * sp;
                ss += sp;
            }
        }
        spsum[i] = ss;
    }
    float* dop = dout + ((((size_t)t * BB + b) * COUT + co)) * 1024;
    #pragma unroll
    for (int p = 0; p < 8; p++) dop[pxbase + p] += outacc[p];

    // Per-node spike mean (per half-block = per c_out)
    float* red = (float*)pair_s;
    for (int i = 0; i < 5; i++) {
        __syncthreads();
        red[tid] = spsum[i];
        __syncthreads();
        for (int off = 64; off; off >>= 1) {
            if (t2 < off) red[tid] += red[tid + off];
            __syncthreads();
        }
        if (t2 == 0) g_msp[((size_t)i * BB + b) * COUT + co] = red[half * 128] * (1.f / 1024.f);
    }
}

// ---------------------------------------------------------------------------
// K5: feats_i = relu(spike_mean @ ft_w^T + ft_b); end-of-step trace update
// ---------------------------------------------------------------------------
__global__ void k5_feats(const float* __restrict__ ftw, const float* __restrict__ ftb) {
    int b = blockIdx.x, tid = threadIdx.x;
    __shared__ float ms[5 * COUT];
    for (int i = 0; i < 5; i++) ms[i * COUT + tid] = g_msp[((size_t)i * BB + b) * COUT + tid];
    __syncthreads();
    float feats[6];
    feats[0] = g_feat0[b * COUT + tid];
    for (int i = 0; i < 5; i++) {
        float f = ftb[tid];
        for (int d = 0; d < COUT; d++) f += ms[i * COUT + d] * ftw[tid * COUT + d];
        feats[i + 1] = fmaxf(f, 0.f);
    }
    for (int n = 0; n < NN; n++) {
        size_t ix = ((size_t)b * NN + n) * COUT + tid;
        g_traces[ix] = 0.6f * g_traces[ix] + 0.4f * feats[n];
    }
}

// ---------------------------------------------------------------------------
extern "C" void kernel_launch(void* const* d_in, const int* in_sizes, int n_in,
                              void* d_out, int out_size) {
    const float* x       = (const float*)d_in[0];
    const float* conv0_w = (const float*)d_in[1];
    const float* bn0_g   = (const float*)d_in[2];
    const float* bn0_b   = (const float*)d_in[3];
    const float* bn0_m   = (const float*)d_in[4];
    const float* bn0_v   = (const float*)d_in[5];
    const float* convs_w = (const float*)d_in[6];
    const float* bns_g   = (const float*)d_in[7];
    const float* bns_b   = (const float*)d_in[8];
    const float* bns_m   = (const float*)d_in[9];
    const float* bns_v   = (const float*)d_in[10];
    const float* plif_w  = (const float*)d_in[11];
    const float* ft_w    = (const float*)d_in[12];
    const float* ft_b    = (const float*)d_in[13];
    const float* gat_W   = (const float*)d_in[14];
    const float* gat_a   = (const float*)d_in[15];
    const float* out_w   = (const float*)d_in[16];
    float* dout = (float*)d_out;

    const int k1_smem = 3 * 66 * 66 * (int)sizeof(float);  // 52272 B
    cudaFuncSetAttribute(k1_conv0, cudaFuncAttributeMaxDynamicSharedMemorySize, k1_smem);

    k0_zero<<<2048, 256>>>();
    for (int t = 0; t < TT; t++) {
        k1_conv0<<<dim3(BB, COUT), 256, k1_smem>>>(x, conv0_w, bn0_g, bn0_b, bn0_m, bn0_v,
                                                   plif_w, out_w, dout, t);
        k2_graph<<<BB, 128>>>(ft_w, ft_b, gat_W, gat_a);
        k3_nodeconv<<<dim3(BB, COUT / 2), 256>>>(convs_w, bns_g, bns_b, bns_m, bns_v,
                                                 plif_w, out_w, dout, t);
        k5_feats<<<BB, 128>>>(ft_w, ft_b);
    }
}

// round 12
// speedup vs baseline: 1.4365x; 1.4365x over previous
#include <cuda_runtime.h>
#include <cuda_bf16.h>
#include <cstddef>
#include <cstdint>

// Problem constants
#define TT 4
#define BB 16
#define CIN 3
#define HIMG 64
#define WIMG 64
#define NN 6
#define COUT 128
#define HP 32
#define WP 32
#define KK 1152          // 128 ic * 9 taps (kk = ic*9 + ky*3 + kx)

// Persistent state
__device__ float g_v0[BB * COUT * HIMG * WIMG];
__device__ float g_vn[5 * BB * COUT * HP * WP];   // [i][b][co][px]
__device__ float g_traces[BB * NN * COUT];
__device__ float g_out0[BB * COUT * HP * WP];
__device__ float g_mean0[BB * COUT];
__device__ float g_feat0[BB * COUT];
__device__ float g_msp[5 * BB * COUT];            // raw spike sums (k5 /1024)
__device__ float g_c[BB * NN];

// Tensor-path scratch
__device__ __nv_bfloat16 g_X[(size_t)BB * 1024 * KK];   // [b][px][kk]
__device__ __nv_bfloat16 g_W[3 * 5 * COUT * KK];        // [split][i][co][kk]

__device__ __forceinline__ float sigf(float x) { return 1.f / (1.f + expf(-x)); }

__device__ __forceinline__ uint32_t smem_u32(const void* p) {
    uint32_t a;
    asm("{ .reg .u64 t; cvta.to.shared.u64 t, %1; cvt.u32.u64 %0, t; }" : "=r"(a) : "l"(p));
    return a;
}
__device__ __forceinline__ void ldm4(uint32_t* r, uint32_t addr) {
    asm volatile("ldmatrix.sync.aligned.m8n8.x4.shared.b16 {%0,%1,%2,%3}, [%4];"
                 : "=r"(r[0]), "=r"(r[1]), "=r"(r[2]), "=r"(r[3]) : "r"(addr));
}
__device__ __forceinline__ void mma16816(float* c, const uint32_t* a,
                                         uint32_t b0, uint32_t b1) {
    asm volatile("mma.sync.aligned.m16n8k16.row.col.f32.bf16.bf16.f32 "
                 "{%0,%1,%2,%3}, {%4,%5,%6,%7}, {%8,%9}, {%0,%1,%2,%3};"
                 : "+f"(c[0]), "+f"(c[1]), "+f"(c[2]), "+f"(c[3])
                 : "r"(a[0]), "r"(a[1]), "r"(a[2]), "r"(a[3]), "r"(b0), "r"(b1));
}

// ---------------------------------------------------------------------------
// K0: zero state
// ---------------------------------------------------------------------------
__global__ void k0_zero() {
    const size_t n0 = (size_t)BB * COUT * HIMG * WIMG;
    const size_t n1 = (size_t)5 * BB * COUT * HP * WP;
    const size_t n2 = (size_t)BB * NN * COUT;
    const size_t tot = n0 + n1 + n2;
    for (size_t i = (size_t)blockIdx.x * blockDim.x + threadIdx.x; i < tot;
         i += (size_t)gridDim.x * blockDim.x) {
        if (i < n0) g_v0[i] = 0.f;
        else if (i < n0 + n1) g_vn[i - n0] = 0.f;
        else g_traces[i - n0 - n1] = 0.f;
    }
}

// ---------------------------------------------------------------------------
// K_wsplit: 3-way bf16 split of node-conv weights (residual <= 2^-25 |w|)
// ---------------------------------------------------------------------------
__global__ void k_wsplit(const float* __restrict__ convw) {
    int gid = blockIdx.x * 256 + threadIdx.x;    // 5*128*1152 = 737280
    if (gid >= 5 * COUT * KK) return;
    float w = convw[gid];
    __nv_bfloat16 h = __float2bfloat16(w);
    float r1 = w - __bfloat162float(h);
    __nv_bfloat16 m = __float2bfloat16(r1);
    float r2 = r1 - __bfloat162float(m);
    __nv_bfloat16 l = __float2bfloat16(r2);
    g_W[gid] = h;
    g_W[5 * COUT * KK + gid] = m;
    g_W[2 * 5 * COUT * KK + gid] = l;
}

// ---------------------------------------------------------------------------
// K_im2col: g_X[b][px][kk] = out0[b][ic][y+ky-1][x+kx-1] (bf16, exact)
// grid (16 b, 32 y), 256 threads, dyn smem = 128*102 floats
// ---------------------------------------------------------------------------
__global__ void k_im2col() {
    extern __shared__ float in_s[];   // [128 ic][3 rows][34 x]
    int b = blockIdx.x, y = blockIdx.y, tid = threadIdx.x;
    for (int idx = tid; idx < 128 * 102; idx += 256) {
        int ic = idx / 102, rem = idx % 102, row = rem / 34, xx = rem % 34;
        int yy = y + row - 1, xg = xx - 1;
        float v = 0.f;
        if ((unsigned)yy < 32u && (unsigned)xg < 32u)
            v = g_out0[((size_t)b * COUT + ic) * 1024 + yy * 32 + xg];
        in_s[idx] = v;
    }
    __syncthreads();
    __nv_bfloat16* dst = g_X + ((size_t)b * 1024 + y * 32) * KK;
    for (int q = tid; q < 32 * 144; q += 256) {
        int x = q / 144, kg = q % 144;
        __nv_bfloat16 tmp[8];
        #pragma unroll
        for (int j = 0; j < 8; j++) {
            int kk = kg * 8 + j;
            int ic = kk / 9, tap = kk - ic * 9;
            int ky = tap / 3, kx = tap - ky * 3;
            tmp[j] = __float2bfloat16(in_s[ic * 102 + ky * 34 + x + kx]);
        }
        *(uint4*)(dst + (size_t)x * KK + kg * 8) = *(const uint4*)tmp;
    }
}

// ---------------------------------------------------------------------------
// K1: conv0(3->128, 3x3, SAME) + BN + PLIF + spike + 2x2 avgpool (scalar)
// ---------------------------------------------------------------------------
__global__ void k1_conv0(const float* __restrict__ x, const float* __restrict__ w0,
                         const float* __restrict__ bg, const float* __restrict__ bb,
                         const float* __restrict__ bm, const float* __restrict__ bv,
                         const float* __restrict__ plw, const float* __restrict__ outw,
                         float* __restrict__ dout, int t) {
    extern __shared__ float tile[];   // [3][66][66]
    __shared__ float ws[27];
    __shared__ float red[256];
    int b = blockIdx.x, c = blockIdx.y, tid = threadIdx.x;

    const float* xb = x + (((size_t)t * BB + b) * CIN) * (HIMG * WIMG);
    for (int idx = tid; idx < 3 * 66 * 66; idx += 256) {
        int ic = idx / 4356, rem = idx % 4356;
        int r = rem / 66, cc = rem % 66;
        int y = r - 1, xx = cc - 1;
        float v = 0.f;
        if ((unsigned)y < 64u && (unsigned)xx < 64u) v = xb[ic * 4096 + y * 64 + xx];
        tile[idx] = v;
    }
    if (tid < 27) ws[tid] = w0[c * 27 + tid];
    __syncthreads();

    float scale = bg[c] / sqrtf(bv[c] + 1e-5f);
    float shift = bb[c] - bm[c] * scale;
    float sg = sigf(plw[0]);
    float wsig0 = sigf(outw[0]);

    float* v0p = g_v0 + ((size_t)b * COUT + c) * (HIMG * WIMG);
    float* o0p = g_out0 + ((size_t)b * COUT + c) * (HP * WP);
    float* dop = dout + ((((size_t)t * BB + b) * COUT + c)) * (HP * WP);

    float lsum = 0.f;
    for (int k = 0; k < 4; k++) {
        int q = tid + k * 256;
        int ph = q >> 5, pw = q & 31;
        float psum = 0.f;
        #pragma unroll
        for (int dy = 0; dy < 2; dy++) {
            #pragma unroll
            for (int dx = 0; dx < 2; dx++) {
                int yy = 2 * ph + dy, xx = 2 * pw + dx;
                float acc = 0.f;
                #pragma unroll
                for (int ic = 0; ic < 3; ic++) {
                    const float* tp = tile + ic * 4356 + yy * 66 + xx;
                    const float* wp = ws + ic * 9;
                    #pragma unroll
                    for (int ky = 0; ky < 3; ky++)
                        #pragma unroll
                        for (int kx = 0; kx < 3; kx++)
                            acc += tp[ky * 66 + kx] * wp[ky * 3 + kx];
                }
                float bnv = acc * scale + shift;
                float vold = v0p[yy * 64 + xx];
                float v = vold + (bnv - vold) * sg;
                float sp = (v >= 1.f) ? 1.f : 0.f;
                v0p[yy * 64 + xx] = (v >= 1.f) ? 0.f : v;
                psum += sp;
            }
        }
        float o = psum * 0.25f;
        o0p[q] = o;
        dop[q] = wsig0 * o;
        lsum += o;
    }
    red[tid] = lsum;
    __syncthreads();
    for (int off = 128; off; off >>= 1) {
        if (tid < off) red[tid] += red[tid + off];
        __syncthreads();
    }
    if (tid == 0) g_mean0[b * COUT + c] = red[0] * (1.f / 1024.f);
}

// ---------------------------------------------------------------------------
// K2: per-batch tiny graph work (+ zero g_msp for this step)
// ---------------------------------------------------------------------------
__global__ void k2_graph(const float* __restrict__ ftw, const float* __restrict__ ftb,
                         const float* __restrict__ gatW, const float* __restrict__ gata) {
    int b = blockIdx.x, tid = threadIdx.x;
    __shared__ float tr[NN * COUT];
    __shared__ float m0[COUT];
    __shared__ float hp[NN * COUT];
    __shared__ float e1[NN * 4], e2[NN * 4];
    __shared__ float attn[36], Sm[36], adj[36], opm[36], dis[NN];

    for (int i = 0; i < 5; i++) g_msp[((size_t)i * BB + b) * COUT + tid] = 0.f;

    m0[tid] = g_mean0[b * COUT + tid];
    for (int n = 0; n < NN; n++) tr[n * COUT + tid] = g_traces[((size_t)b * NN + n) * COUT + tid];
    __syncthreads();

    float f = ftb[tid];
    for (int d = 0; d < COUT; d++) f += m0[d] * ftw[tid * COUT + d];
    f = fmaxf(f, 0.f);
    g_feat0[b * COUT + tid] = f;
    float t0 = 0.6f * tr[tid] + 0.4f * f;
    tr[tid] = t0;
    g_traces[(size_t)b * NN * COUT + tid] = t0;
    __syncthreads();

    for (int n = 0; n < NN; n++) {
        float s = 0.f;
        for (int k = 0; k < COUT; k++) s += tr[n * COUT + k] * gatW[tid * COUT + k];
        hp[n * COUT + tid] = s;
    }
    __syncthreads();

    if (tid < NN * 4) {
        int n = tid >> 2, h = tid & 3;
        float s1 = 0.f, s2 = 0.f;
        for (int d = 0; d < 32; d++) {
            float hv = hp[n * COUT + h * 32 + d];
            s1 += hv * gata[h * 64 + d];
            s2 += hv * gata[h * 64 + 32 + d];
        }
        e1[tid] = s1;
        e2[tid] = s2;
    }
    __syncthreads();

    if (tid < 36) {
        int i = tid / 6, j = tid % 6;
        float s = 0.f;
        for (int h = 0; h < 4; h++) {
            float x1 = e1[i * 4 + h] + e2[j * 4 + h];
            float x2 = e1[j * 4 + h] + e2[i * 4 + h];
            x1 = x1 > 0.f ? x1 : 0.2f * x1;
            x2 = x2 > 0.f ? x2 : 0.2f * x2;
            s += 0.5f * (x1 + x2);
        }
        attn[tid] = s * 0.25f;
    }
    __syncthreads();

    if (tid < NN) {
        int i = tid;
        float mx = -1e30f;
        for (int j = 0; j < 6; j++) mx = fmaxf(mx, attn[i * 6 + j] * 100.f);
        float ex[6], sum = 0.f;
        for (int j = 0; j < 6; j++) { ex[j] = expf(attn[i * 6 + j] * 100.f - mx); sum += ex[j]; }
        for (int j = 0; j < 6; j++) Sm[i * 6 + j] = ex[j] / sum;
    }
    __syncthreads();

    if (tid < NN) {
        int i = tid;
        float a[6];
        for (int j = 0; j < 6; j++) a[j] = Sm[i * 6 + j];
        float kth = 0.f;
        for (int r = 0; r < 3; r++) {
            int bi = 0; float bvv = -1e30f;
            for (int j = 0; j < 6; j++) if (a[j] > bvv) { bvv = a[j]; bi = j; }
            kth = bvv; a[bi] = -1e30f;
        }
        for (int j = 0; j < 6; j++) Sm[i * 6 + j] = (Sm[i * 6 + j] >= kth) ? Sm[i * 6 + j] : 0.f;
    }
    __syncthreads();

    if (tid < 36) { int i = tid / 6, j = tid % 6; adj[tid] = 0.5f * (Sm[i * 6 + j] + Sm[j * 6 + i]); }
    __syncthreads();
    if (tid < NN) {
        float s = 0.f;
        for (int j = 0; j < 6; j++) s += adj[tid * 6 + j];
        dis[tid] = 1.f / sqrtf(s + 1e-6f);
    }
    __syncthreads();
    if (tid < 36) { int i = tid / 6, j = tid % 6; opm[tid] = dis[i] * adj[tid] * dis[j]; }
    __syncthreads();
    if (tid < NN) {
        float s = 0.f;
        for (int j = 0; j < 6; j++) s += opm[tid * 6 + j] * opm[j * 6 + 0];
        g_c[b * NN + tid] = s;
    }
}

// ---------------------------------------------------------------------------
// K3M: warp-MMA node conv. Per CTA: D[128 px][128 co] = X·W^T, K=1152 x3 splits.
// 8 warps (2 M x 4 N); warp tile 64x32; K chunks of 64 staged in smem.
// ---------------------------------------------------------------------------
#define XBYTES 18432                 // 128 rows x 72 bf16 x 2
#define WBYTES 18432
#define SS_OFF  73728                // spike sums (128 floats)
#define CS_OFF  74240                // cs (128 floats)
#define SH_OFF  74752                // sh (128 floats)
#define SMEMT   75264
#define DSTRIDE 134

__global__ void __launch_bounds__(256) k3m_nodeconv(
    const float* __restrict__ bg, const float* __restrict__ bb,
    const float* __restrict__ bm, const float* __restrict__ bv,
    const float* __restrict__ plw, const float* __restrict__ outw,
    float* __restrict__ dout, int t) {
    extern __shared__ char smem[];
    uint32_t sb = smem_u32(smem);
    int tid = threadIdx.x;
    int wid = tid >> 5, lane = tid & 31;
    int wm = wid >> 2, wn = wid & 3;
    int b = blockIdx.x >> 3, pxt = blockIdx.x & 7;
    int pxbase = pxt * 128;

    // ldmatrix base addresses
    uint32_t a_row = (uint32_t)(wm * 64 + (lane & 15));
    uint32_t lcol = (uint32_t)((lane >> 4) * 8);
    uint32_t sxa = sb + (a_row * 72 + lcol) * 2;
    uint32_t b_row = (uint32_t)(wn * 32 + (lane & 15));
    uint32_t sba = sb + XBYTES + (b_row * 72 + lcol) * 2;

    const __nv_bfloat16* xsrc = g_X + ((size_t)b * 1024 + pxbase) * KK;
    float* Dsm = (float*)smem;
    float* ssm = (float*)(smem + SS_OFF);
    float* csm = (float*)(smem + CS_OFF);
    float* shm = (float*)(smem + SH_OFF);
    int gp = lane >> 2, tg = lane & 3;

    for (int node = 0; node < 5; node++) {
        float acc[4][4][4];
        #pragma unroll
        for (int mt = 0; mt < 4; mt++)
            #pragma unroll
            for (int nt = 0; nt < 4; nt++)
                #pragma unroll
                for (int u = 0; u < 4; u++) acc[mt][nt][u] = 0.f;

        for (int c = 0; c < 18; c++) {
            __syncthreads();
            // stage X chunk (128 px x 64 kk)
            for (int idx = tid; idx < 1024; idx += 256) {
                int px = idx >> 3, seg = idx & 7;
                uint4 v = *(const uint4*)(xsrc + (size_t)px * KK + c * 64 + seg * 8);
                *(uint4*)(smem + (px * 72 + seg * 8) * 2) = v;
            }
            // stage W chunks for 3 splits (128 co x 64 kk each)
            for (int idx = tid; idx < 3072; idx += 256) {
                int s = idx >> 10, r = idx & 1023;
                int co = r >> 3, seg = r & 7;
                const __nv_bfloat16* wsrc =
                    g_W + ((((size_t)s * 5 + node) * COUT + co) * KK) + c * 64 + seg * 8;
                uint4 v = *(const uint4*)wsrc;
                *(uint4*)(smem + XBYTES + s * WBYTES + (co * 72 + seg * 8) * 2) = v;
            }
            __syncthreads();
            #pragma unroll
            for (int ks = 0; ks < 4; ks++) {
                uint32_t afr[4][4];
                #pragma unroll
                for (int mt = 0; mt < 4; mt++)
                    ldm4(afr[mt], sxa + (uint32_t)(mt * 16 * 72 + ks * 16) * 2);
                #pragma unroll
                for (int s = 0; s < 3; s++) {
                    #pragma unroll
                    for (int ntg = 0; ntg < 2; ntg++) {
                        uint32_t bfr[4];
                        ldm4(bfr, sba + (uint32_t)(s * WBYTES) +
                                  (uint32_t)(ntg * 16 * 72 + ks * 16) * 2);
                        #pragma unroll
                        for (int mt = 0; mt < 4; mt++) {
                            mma16816(acc[mt][ntg * 2 + 0], afr[mt], bfr[0], bfr[2]);
                            mma16816(acc[mt][ntg * 2 + 1], afr[mt], bfr[1], bfr[3]);
                        }
                    }
                }
            }
        }
        __syncthreads();   // mainloop smem reads done; reuse as D tile

        // per-node params + zero spike sums
        float ci = g_c[b * NN + node + 1];
        float sg = sigf(plw[node + 1]);
        float wsg = sigf(outw[node + 1]);
        if (tid < 128) {
            float sc = bg[node * COUT + tid] / sqrtf(bv[node * COUT + tid] + 1e-5f);
            csm[tid] = ci * sc;
            shm[tid] = bb[node * COUT + tid] - bm[node * COUT + tid] * sc;
            ssm[tid] = 0.f;
        }
        // fragments -> Dsm[px][co]
        #pragma unroll
        for (int mt = 0; mt < 4; mt++) {
            #pragma unroll
            for (int nt = 0; nt < 4; nt++) {
                int px0 = wm * 64 + mt * 16 + gp;
                int co0 = wn * 32 + nt * 8 + tg * 2;
                *(float2*)&Dsm[px0 * DSTRIDE + co0] =
                    make_float2(acc[mt][nt][0], acc[mt][nt][1]);
                *(float2*)&Dsm[(px0 + 8) * DSTRIDE + co0] =
                    make_float2(acc[mt][nt][2], acc[mt][nt][3]);
            }
        }
        __syncthreads();

        // coalesced PLIF epilogue
        float* vn0 = g_vn + (((size_t)node * BB + b) * COUT) * 1024 + pxbase;
        float* do0 = dout + (((size_t)t * BB + b) * COUT) * 1024 + pxbase;
        #pragma unroll 4
        for (int rep = 0; rep < 64; rep++) {
            int idxq = rep * 256 + tid;
            int co = idxq >> 7, px = idxq & 127;
            float val = Dsm[px * DSTRIDE + co];
            float y = val * csm[co] + shm[co];
            float* vp = vn0 + (size_t)co * 1024 + px;
            float vold = *vp;
            float v = vold + (y - vold) * sg;
            float sp = (v >= 1.f) ? 1.f : 0.f;
            *vp = (v >= 1.f) ? 0.f : v;
            do0[(size_t)co * 1024 + px] += wsg * sp;
            float rr = sp;
            #pragma unroll
            for (int o = 16; o; o >>= 1) rr += __shfl_xor_sync(0xffffffffu, rr, o);
            if (lane == 0) atomicAdd(&ssm[co], rr);
        }
        __syncthreads();
        if (tid < 128)
            atomicAdd(&g_msp[((size_t)node * BB + b) * COUT + tid], ssm[tid]);
    }
}

// ---------------------------------------------------------------------------
// K5: feats_i = relu(spike_sum/1024 @ ft_w^T + ft_b); end-of-step trace update
// ---------------------------------------------------------------------------
__global__ void k5_feats(const float* __restrict__ ftw, const float* __restrict__ ftb) {
    int b = blockIdx.x, tid = threadIdx.x;
    __shared__ float ms[5 * COUT];
    for (int i = 0; i < 5; i++)
        ms[i * COUT + tid] = g_msp[((size_t)i * BB + b) * COUT + tid] * (1.f / 1024.f);
    __syncthreads();
    float feats[6];
    feats[0] = g_feat0[b * COUT + tid];
    for (int i = 0; i < 5; i++) {
        float f = ftb[tid];
        for (int d = 0; d < COUT; d++) f += ms[i * COUT + d] * ftw[tid * COUT + d];
        feats[i + 1] = fmaxf(f, 0.f);
    }
    for (int n = 0; n < NN; n++) {
        size_t ix = ((size_t)b * NN + n) * COUT + tid;
        g_traces[ix] = 0.6f * g_traces[ix] + 0.4f * feats[n];
    }
}

// ---------------------------------------------------------------------------
extern "C" void kernel_launch(void* const* d_in, const int* in_sizes, int n_in,
                              void* d_out, int out_size) {
    const float* x       = (const float*)d_in[0];
    const float* conv0_w = (const float*)d_in[1];
    const float* bn0_g   = (const float*)d_in[2];
    const float* bn0_b   = (const float*)d_in[3];
    const float* bn0_m   = (const float*)d_in[4];
    const float* bn0_v   = (const float*)d_in[5];
    const float* convs_w = (const float*)d_in[6];
    const float* bns_g   = (const float*)d_in[7];
    const float* bns_b   = (const float*)d_in[8];
    const float* bns_m   = (const float*)d_in[9];
    const float* bns_v   = (const float*)d_in[10];
    const float* plif_w  = (const float*)d_in[11];
    const float* ft_w    = (const float*)d_in[12];
    const float* ft_b    = (const float*)d_in[13];
    const float* gat_W   = (const float*)d_in[14];
    const float* gat_a   = (const float*)d_in[15];
    const float* out_w   = (const float*)d_in[16];
    float* dout = (float*)d_out;

    const int k1_smem = 3 * 66 * 66 * (int)sizeof(float);       // 52272 B
    const int i2c_smem = 128 * 102 * (int)sizeof(float);        // 52224 B
    cudaFuncSetAttribute(k1_conv0, cudaFuncAttributeMaxDynamicSharedMemorySize, k1_smem);
    cudaFuncSetAttribute(k_im2col, cudaFuncAttributeMaxDynamicSharedMemorySize, i2c_smem);
    cudaFuncSetAttribute(k3m_nodeconv, cudaFuncAttributeMaxDynamicSharedMemorySize, SMEMT);

    k0_zero<<<2048, 256>>>();
    k_wsplit<<<(5 * COUT * KK + 255) / 256, 256>>>(convs_w);
    for (int t = 0; t < TT; t++) {
        k1_conv0<<<dim3(BB, COUT), 256, k1_smem>>>(x, conv0_w, bn0_g, bn0_b, bn0_m, bn0_v,
                                                   plif_w, out_w, dout, t);
        k2_graph<<<BB, 128>>>(ft_w, ft_b, gat_W, gat_a);
        k_im2col<<<dim3(BB, 32), 256, i2c_smem>>>();
        k3m_nodeconv<<<128, 256, SMEMT>>>(bns_g, bns_b, bns_m, bns_v,
                                          plif_w, out_w, dout, t);
        k5_feats<<<BB, 128>>>(ft_w, ft_b);
    }
}

// round 15
// speedup vs baseline: 1.6175x; 1.1260x over previous
#include <cuda_runtime.h>
#include <cuda_fp16.h>
#include <cuda_bf16.h>
#include <cstddef>
#include <cstdint>

// Problem constants
#define TT 4
#define BB 16
#define CIN 3
#define HIMG 64
#define WIMG 64
#define NN 6
#define COUT 128
#define HP 32
#define WP 32
#define KK 1152          // 128 ic * 9 taps (kk = ic*9 + ky*3 + kx)

// Persistent state
__device__ float g_v0[BB * COUT * HIMG * WIMG];
__device__ float g_vn[5 * BB * COUT * HP * WP];   // [i][b][co][px]
__device__ float g_traces[BB * NN * COUT];
__device__ float g_out0[BB * COUT * HP * WP];
__device__ float g_mean0[BB * COUT];
__device__ float g_feat0[BB * COUT];
__device__ float g_msp[5 * BB * COUT];            // raw spike sums (k5 /1024)
__device__ float g_c[BB * NN];

// Tensor-path scratch
__device__ __half g_X[(size_t)BB * 1024 * KK];    // [b][px][kk]
__device__ __half g_W[2 * 5 * COUT * KK];         // [split][i][co][kk] fp16 2-split
__device__ float g_ftwT[COUT * COUT];             // ftw transposed [d][co]
__device__ float g_gatWT[COUT * COUT];            // gatW transposed [k][co]

__device__ __forceinline__ float sigf(float x) { return 1.f / (1.f + expf(-x)); }

__device__ __forceinline__ uint32_t smem_u32(const void* p) {
    uint32_t a;
    asm("{ .reg .u64 t; cvta.to.shared.u64 t, %1; cvt.u32.u64 %0, t; }" : "=r"(a) : "l"(p));
    return a;
}
__device__ __forceinline__ void ldm4(uint32_t* r, uint32_t addr) {
    asm volatile("ldmatrix.sync.aligned.m8n8.x4.shared.b16 {%0,%1,%2,%3}, [%4];"
                 : "=r"(r[0]), "=r"(r[1]), "=r"(r[2]), "=r"(r[3]) : "r"(addr));
}
__device__ __forceinline__ void mma16816(float* c, const uint32_t* a,
                                         uint32_t b0, uint32_t b1) {
    asm volatile("mma.sync.aligned.m16n8k16.row.col.f32.f16.f16.f32 "
                 "{%0,%1,%2,%3}, {%4,%5,%6,%7}, {%8,%9}, {%0,%1,%2,%3};"
                 : "+f"(c[0]), "+f"(c[1]), "+f"(c[2]), "+f"(c[3])
                 : "r"(a[0]), "r"(a[1]), "r"(a[2]), "r"(a[3]), "r"(b0), "r"(b1));
}
__device__ __forceinline__ void cpa16(uint32_t d, const void* g) {
    asm volatile("cp.async.cg.shared.global [%0], [%1], 16;" :: "r"(d), "l"(g));
}
#define CPA_COMMIT() asm volatile("cp.async.commit_group;" ::: "memory")
#define CPA_WAIT1()  asm volatile("cp.async.wait_group 1;" ::: "memory")

// ---------------------------------------------------------------------------
// K0: zero state
// ---------------------------------------------------------------------------
__global__ void k0_zero() {
    const size_t n0 = (size_t)BB * COUT * HIMG * WIMG;
    const size_t n1 = (size_t)5 * BB * COUT * HP * WP;
    const size_t n2 = (size_t)BB * NN * COUT;
    const size_t tot = n0 + n1 + n2;
    for (size_t i = (size_t)blockIdx.x * blockDim.x + threadIdx.x; i < tot;
         i += (size_t)gridDim.x * blockDim.x) {
        if (i < n0) g_v0[i] = 0.f;
        else if (i < n0 + n1) g_vn[i - n0] = 0.f;
        else g_traces[i - n0 - n1] = 0.f;
    }
}

// ---------------------------------------------------------------------------
// K_wsplit: 2-way fp16 split of node-conv weights (residual <= ~2^-22 |w|)
// ---------------------------------------------------------------------------
__global__ void k_wsplit(const float* __restrict__ convw) {
    int gid = blockIdx.x * 256 + threadIdx.x;    // 5*128*1152 = 737280
    if (gid >= 5 * COUT * KK) return;
    float w = convw[gid];
    __half h = __float2half_rn(w);
    float r1 = w - __half2float(h);
    __half l = __float2half_rn(r1);
    g_W[gid] = h;
    g_W[5 * COUT * KK + gid] = l;
}

// ---------------------------------------------------------------------------
// K_wtrans: transpose ft_w and gat_W once for coalesced matvec access
// ---------------------------------------------------------------------------
__global__ void k_wtrans(const float* __restrict__ ftw, const float* __restrict__ gatW) {
    int i = blockIdx.x * 256 + threadIdx.x;
    if (i < COUT * COUT) {
        int r = i >> 7, c = i & 127;
        g_ftwT[c * COUT + r] = ftw[i];
        g_gatWT[c * COUT + r] = gatW[i];
    }
}

// ---------------------------------------------------------------------------
// K_im2col: g_X[b][px][kk] = out0[b][ic][y+ky-1][x+kx-1] (fp16, exact)
// grid (16 b, 32 y), 256 threads, dyn smem = 128*102 floats
// ---------------------------------------------------------------------------
__global__ void k_im2col() {
    extern __shared__ float in_s[];   // [128 ic][3 rows][34 x]
    int b = blockIdx.x, y = blockIdx.y, tid = threadIdx.x;
    for (int idx = tid; idx < 128 * 102; idx += 256) {
        int ic = idx / 102, rem = idx % 102, row = rem / 34, xx = rem % 34;
        int yy = y + row - 1, xg = xx - 1;
        float v = 0.f;
        if ((unsigned)yy < 32u && (unsigned)xg < 32u)
            v = g_out0[((size_t)b * COUT + ic) * 1024 + yy * 32 + xg];
        in_s[idx] = v;
    }
    __syncthreads();
    __half* dst = g_X + ((size_t)b * 1024 + y * 32) * KK;
    for (int q = tid; q < 32 * 144; q += 256) {
        int x = q / 144, kg = q % 144;
        __half tmp[8];
        #pragma unroll
        for (int j = 0; j < 8; j++) {
            int kk = kg * 8 + j;
            int ic = kk / 9, tap = kk - ic * 9;
            int ky = tap / 3, kx = tap - ky * 3;
            tmp[j] = __float2half_rn(in_s[ic * 102 + ky * 34 + x + kx]);
        }
        *(uint4*)(dst + (size_t)x * KK + kg * 8) = *(const uint4*)tmp;
    }
}

// ---------------------------------------------------------------------------
// K1: conv0(3->128, 3x3, SAME) + BN + PLIF + spike + 2x2 avgpool (scalar)
// ---------------------------------------------------------------------------
__global__ void k1_conv0(const float* __restrict__ x, const float* __restrict__ w0,
                         const float* __restrict__ bg, const float* __restrict__ bb,
                         const float* __restrict__ bm, const float* __restrict__ bv,
                         const float* __restrict__ plw, const float* __restrict__ outw,
                         float* __restrict__ dout, int t) {
    extern __shared__ float tile[];   // [3][66][66]
    __shared__ float ws[27];
    __shared__ float red[256];
    int b = blockIdx.x, c = blockIdx.y, tid = threadIdx.x;

    const float* xb = x + (((size_t)t * BB + b) * CIN) * (HIMG * WIMG);
    for (int idx = tid; idx < 3 * 66 * 66; idx += 256) {
        int ic = idx / 4356, rem = idx % 4356;
        int r = rem / 66, cc = rem % 66;
        int y = r - 1, xx = cc - 1;
        float v = 0.f;
        if ((unsigned)y < 64u && (unsigned)xx < 64u) v = xb[ic * 4096 + y * 64 + xx];
        tile[idx] = v;
    }
    if (tid < 27) ws[tid] = w0[c * 27 + tid];
    __syncthreads();

    float scale = bg[c] / sqrtf(bv[c] + 1e-5f);
    float shift = bb[c] - bm[c] * scale;
    float sg = sigf(plw[0]);
    float wsig0 = sigf(outw[0]);

    float* v0p = g_v0 + ((size_t)b * COUT + c) * (HIMG * WIMG);
    float* o0p = g_out0 + ((size_t)b * COUT + c) * (HP * WP);
    float* dop = dout + ((((size_t)t * BB + b) * COUT + c)) * (HP * WP);

    float lsum = 0.f;
    for (int k = 0; k < 4; k++) {
        int q = tid + k * 256;
        int ph = q >> 5, pw = q & 31;
        float psum = 0.f;
        #pragma unroll
        for (int dy = 0; dy < 2; dy++) {
            #pragma unroll
            for (int dx = 0; dx < 2; dx++) {
                int yy = 2 * ph + dy, xx = 2 * pw + dx;
                float acc = 0.f;
                #pragma unroll
                for (int ic = 0; ic < 3; ic++) {
                    const float* tp = tile + ic * 4356 + yy * 66 + xx;
                    const float* wp = ws + ic * 9;
                    #pragma unroll
                    for (int ky = 0; ky < 3; ky++)
                        #pragma unroll
                        for (int kx = 0; kx < 3; kx++)
                            acc += tp[ky * 66 + kx] * wp[ky * 3 + kx];
                }
                float bnv = acc * scale + shift;
                float vold = v0p[yy * 64 + xx];
                float v = vold + (bnv - vold) * sg;
                float sp = (v >= 1.f) ? 1.f : 0.f;
                v0p[yy * 64 + xx] = (v >= 1.f) ? 0.f : v;
                psum += sp;
            }
        }
        float o = psum * 0.25f;
        o0p[q] = o;
        dop[q] = wsig0 * o;
        lsum += o;
    }
    red[tid] = lsum;
    __syncthreads();
    for (int off = 128; off; off >>= 1) {
        if (tid < off) red[tid] += red[tid + off];
        __syncthreads();
    }
    if (tid == 0) g_mean0[b * COUT + c] = red[0] * (1.f / 1024.f);
}

// ---------------------------------------------------------------------------
// K2: per-batch tiny graph work (+ zero g_msp). Coalesced matvecs via g_*T.
// ---------------------------------------------------------------------------
__global__ void k2_graph(const float* __restrict__ ftb, const float* __restrict__ gata) {
    int b = blockIdx.x, tid = threadIdx.x;
    __shared__ float tr[NN * COUT];
    __shared__ float m0[COUT];
    __shared__ float hp[NN * COUT];
    __shared__ float e1[NN * 4], e2[NN * 4];
    __shared__ float attn[36], Sm[36], adj[36], opm[36], dis[NN];

    for (int i = 0; i < 5; i++) g_msp[((size_t)i * BB + b) * COUT + tid] = 0.f;

    m0[tid] = g_mean0[b * COUT + tid];
    for (int n = 0; n < NN; n++) tr[n * COUT + tid] = g_traces[((size_t)b * NN + n) * COUT + tid];
    __syncthreads();

    // feat0 = relu(mean0 @ ft_w^T + ft_b)  -- coalesced via ftwT
    float f = ftb[tid];
    #pragma unroll 8
    for (int d = 0; d < COUT; d++) f += m0[d] * g_ftwT[d * COUT + tid];
    f = fmaxf(f, 0.f);
    g_feat0[b * COUT + tid] = f;
    float t0 = 0.6f * tr[tid] + 0.4f * f;
    tr[tid] = t0;
    g_traces[(size_t)b * NN * COUT + tid] = t0;
    __syncthreads();

    // hp[n][tid] = sum_k tr[n][k] * gatW[tid][k]  -- coalesced via gatWT, 6-way ILP
    {
        float s[NN];
        #pragma unroll
        for (int n = 0; n < NN; n++) s[n] = 0.f;
        #pragma unroll 4
        for (int k = 0; k < COUT; k++) {
            float w = g_gatWT[k * COUT + tid];
            #pragma unroll
            for (int n = 0; n < NN; n++) s[n] += tr[n * COUT + k] * w;
        }
        #pragma unroll
        for (int n = 0; n < NN; n++) hp[n * COUT + tid] = s[n];
    }
    __syncthreads();

    if (tid < NN * 4) {
        int n = tid >> 2, h = tid & 3;
        float s1 = 0.f, s2 = 0.f;
        for (int d = 0; d < 32; d++) {
            float hv = hp[n * COUT + h * 32 + d];
            s1 += hv * gata[h * 64 + d];
            s2 += hv * gata[h * 64 + 32 + d];
        }
        e1[tid] = s1;
        e2[tid] = s2;
    }
    __syncthreads();

    if (tid < 36) {
        int i = tid / 6, j = tid % 6;
        float s = 0.f;
        for (int h = 0; h < 4; h++) {
            float x1 = e1[i * 4 + h] + e2[j * 4 + h];
            float x2 = e1[j * 4 + h] + e2[i * 4 + h];
            x1 = x1 > 0.f ? x1 : 0.2f * x1;
            x2 = x2 > 0.f ? x2 : 0.2f * x2;
            s += 0.5f * (x1 + x2);
        }
        attn[tid] = s * 0.25f;
    }
    __syncthreads();

    if (tid < NN) {
        int i = tid;
        float mx = -1e30f;
        for (int j = 0; j < 6; j++) mx = fmaxf(mx, attn[i * 6 + j] * 100.f);
        float ex[6], sum = 0.f;
        for (int j = 0; j < 6; j++) { ex[j] = expf(attn[i * 6 + j] * 100.f - mx); sum += ex[j]; }
        for (int j = 0; j < 6; j++) Sm[i * 6 + j] = ex[j] / sum;
    }
    __syncthreads();

    if (tid < NN) {
        int i = tid;
        float a[6];
        for (int j = 0; j < 6; j++) a[j] = Sm[i * 6 + j];
        float kth = 0.f;
        for (int r = 0; r < 3; r++) {
            int bi = 0; float bvv = -1e30f;
            for (int j = 0; j < 6; j++) if (a[j] > bvv) { bvv = a[j]; bi = j; }
            kth = bvv; a[bi] = -1e30f;
        }
        for (int j = 0; j < 6; j++) Sm[i * 6 + j] = (Sm[i * 6 + j] >= kth) ? Sm[i * 6 + j] : 0.f;
    }
    __syncthreads();

    if (tid < 36) { int i = tid / 6, j = tid % 6; adj[tid] = 0.5f * (Sm[i * 6 + j] + Sm[j * 6 + i]); }
    __syncthreads();
    if (tid < NN) {
        float s = 0.f;
        for (int j = 0; j < 6; j++) s += adj[tid * 6 + j];
        dis[tid] = 1.f / sqrtf(s + 1e-6f);
    }
    __syncthreads();
    if (tid < 36) { int i = tid / 6, j = tid % 6; opm[tid] = dis[i] * adj[tid] * dis[j]; }
    __syncthreads();
    if (tid < NN) {
        float s = 0.f;
        for (int j = 0; j < 6; j++) s += opm[tid * 6 + j] * opm[j * 6 + 0];
        g_c[b * NN + tid] = s;
    }
}

// ---------------------------------------------------------------------------
// K3M: warp-MMA node conv, fp16 2-split, cp.async double-buffered pipeline.
// Per CTA: D[128 px][128 co]; 8 warps (2M x 4N); K chunks of 64.
// 90 flattened (node, chunk) iterations; prefetch it+1 while computing it.
// ---------------------------------------------------------------------------
#define BUFB   55296                 // per buffer: X 18432 + 2 W splits * 18432
#define WOFF   18432
#define WSZ    18432
#define D_OFF  110592                // D tile after both buffers
#define SS_OFF 179200                // 110592 + 128*134*4
#define CS_OFF 179712
#define SH_OFF 180224
#define SMEMT  180736
#define DSTRIDE 134

__device__ __forceinline__ void k3_stage(char* smem, int buf, int tid, int node, int c,
                                         const __half* xsrc) {
    char* base = smem + buf * BUFB;
    #pragma unroll
    for (int rep = 0; rep < 4; rep++) {
        int idx = rep * 256 + tid;
        int px = idx >> 3, seg = idx & 7;
        cpa16(smem_u32(base + (px * 72 + seg * 8) * 2),
              xsrc + (size_t)px * KK + c * 64 + seg * 8);
    }
    #pragma unroll
    for (int rep = 0; rep < 8; rep++) {
        int idx = rep * 256 + tid;
        int s = idx >> 10, r = idx & 1023;
        int co = r >> 3, seg = r & 7;
        cpa16(smem_u32(base + WOFF + s * WSZ + (co * 72 + seg * 8) * 2),
              g_W + ((((size_t)s * 5 + node) * COUT + co) * KK) + c * 64 + seg * 8);
    }
}

__global__ void __launch_bounds__(256) k3m_nodeconv(
    const float* __restrict__ bg, const float* __restrict__ bb,
    const float* __restrict__ bm, const float* __restrict__ bv,
    const float* __restrict__ plw, const float* __restrict__ outw,
    float* __restrict__ dout, int t) {
    extern __shared__ char smem[];
    int tid = threadIdx.x;
    int wid = tid >> 5, lane = tid & 31;
    int wm = wid >> 2, wn = wid & 3;
    int b = blockIdx.x >> 3, pxt = blockIdx.x & 7;
    int pxbase = pxt * 128;

    const __half* xsrc = g_X + ((size_t)b * 1024 + pxbase) * KK;
    float* Dsm = (float*)(smem + D_OFF);
    float* ssm = (float*)(smem + SS_OFF);
    float* csm = (float*)(smem + CS_OFF);
    float* shm = (float*)(smem + SH_OFF);
    int gp = lane >> 2, tg = lane & 3;
    uint32_t lrow_off = (uint32_t)(((lane & 15) * 72 + (lane >> 4) * 8) * 2);

    float acc[4][4][4];

    k3_stage(smem, 0, tid, 0, 0, xsrc);
    CPA_COMMIT();

    for (int it = 0; it < 90; it++) {
        int node = it / 18, c = it % 18;
        if (it + 1 < 90)
            k3_stage(smem, (it + 1) & 1, tid, (it + 1) / 18, (it + 1) % 18, xsrc);
        CPA_COMMIT();
        CPA_WAIT1();
        __syncthreads();

        if (c == 0) {
            #pragma unroll
            for (int mt = 0; mt < 4; mt++)
                #pragma unroll
                for (int nt = 0; nt < 4; nt++)
                    #pragma unroll
                    for (int u = 0; u < 4; u++) acc[mt][nt][u] = 0.f;
        }

        char* base = smem + (it & 1) * BUFB;
        uint32_t sxa = smem_u32(base) + (uint32_t)(wm * 64 * 72 * 2) + lrow_off;
        uint32_t sba = smem_u32(base + WOFF) + (uint32_t)(wn * 32 * 72 * 2) + lrow_off;

        #pragma unroll
        for (int ks = 0; ks < 4; ks++) {
            uint32_t afr[4][4];
            #pragma unroll
            for (int mt = 0; mt < 4; mt++)
                ldm4(afr[mt], sxa + (uint32_t)((mt * 16 * 72 + ks * 16) * 2));
            #pragma unroll
            for (int s = 0; s < 2; s++) {
                #pragma unroll
                for (int ntg = 0; ntg < 2; ntg++) {
                    uint32_t bfr[4];
                    ldm4(bfr, sba + (uint32_t)(s * WSZ) +
                              (uint32_t)((ntg * 16 * 72 + ks * 16) * 2));
                    #pragma unroll
                    for (int mt = 0; mt < 4; mt++) {
                        mma16816(acc[mt][ntg * 2 + 0], afr[mt], bfr[0], bfr[2]);
                        mma16816(acc[mt][ntg * 2 + 1], afr[mt], bfr[1], bfr[3]);
                    }
                }
            }
        }

        if (c == 17) {
            // ---- node epilogue (D region is disjoint from prefetch buffers) ----
            float ci = g_c[b * NN + node + 1];
            float sg = sigf(plw[node + 1]);
            float wsg = sigf(outw[node + 1]);
            if (tid < 128) {
                float sc = bg[node * COUT + tid] / sqrtf(bv[node * COUT + tid] + 1e-5f);
                csm[tid] = ci * sc;
                shm[tid] = bb[node * COUT + tid] - bm[node * COUT + tid] * sc;
                ssm[tid] = 0.f;
            }
            #pragma unroll
            for (int mt = 0; mt < 4; mt++) {
                #pragma unroll
                for (int nt = 0; nt < 4; nt++) {
                    int px0 = wm * 64 + mt * 16 + gp;
                    int co0 = wn * 32 + nt * 8 + tg * 2;
                    *(float2*)&Dsm[px0 * DSTRIDE + co0] =
                        make_float2(acc[mt][nt][0], acc[mt][nt][1]);
                    *(float2*)&Dsm[(px0 + 8) * DSTRIDE + co0] =
                        make_float2(acc[mt][nt][2], acc[mt][nt][3]);
                }
            }
            __syncthreads();

            float* vn0 = g_vn + (((size_t)node * BB + b) * COUT) * 1024 + pxbase;
            float* do0 = dout + (((size_t)t * BB + b) * COUT) * 1024 + pxbase;
            #pragma unroll 4
            for (int rep = 0; rep < 64; rep++) {
                int idxq = rep * 256 + tid;
                int co = idxq >> 7, px = idxq & 127;
                float val = Dsm[px * DSTRIDE + co];
                float y = val * csm[co] + shm[co];
                float* vp = vn0 + (size_t)co * 1024 + px;
                float vold = *vp;
                float v = vold + (y - vold) * sg;
                float sp = (v >= 1.f) ? 1.f : 0.f;
                *vp = (v >= 1.f) ? 0.f : v;
                do0[(size_t)co * 1024 + px] += wsg * sp;
                float rr = sp;
                #pragma unroll
                for (int o = 16; o; o >>= 1) rr += __shfl_xor_sync(0xffffffffu, rr, o);
                if (lane == 0) atomicAdd(&ssm[co], rr);
            }
            __syncthreads();
            if (tid < 128)
                atomicAdd(&g_msp[((size_t)node * BB + b) * COUT + tid], ssm[tid]);
        }
        __syncthreads();
    }
}

// ---------------------------------------------------------------------------
// K5: feats_i = relu(spike_sum/1024 @ ft_w^T + ft_b); trace update (coalesced)
// ---------------------------------------------------------------------------
__global__ void k5_feats(const float* __restrict__ ftb) {
    int b = blockIdx.x, tid = threadIdx.x;
    __shared__ float ms[5 * COUT];
    for (int i = 0; i < 5; i++)
        ms[i * COUT + tid] = g_msp[((size_t)i * BB + b) * COUT + tid] * (1.f / 1024.f);
    __syncthreads();
    float feats[6];
    feats[0] = g_feat0[b * COUT + tid];
    {
        float s[5];
        #pragma unroll
        for (int i = 0; i < 5; i++) s[i] = ftb[tid];
        #pragma unroll 4
        for (int d = 0; d < COUT; d++) {
            float w = g_ftwT[d * COUT + tid];
            #pragma unroll
            for (int i = 0; i < 5; i++) s[i] += ms[i * COUT + d] * w;
        }
        #pragma unroll
        for (int i = 0; i < 5; i++) feats[i + 1] = fmaxf(s[i], 0.f);
    }
    for (int n = 0; n < NN; n++) {
        size_t ix = ((size_t)b * NN + n) * COUT + tid;
        g_traces[ix] = 0.6f * g_traces[ix] + 0.4f * feats[n];
    }
}

// ---------------------------------------------------------------------------
extern "C" void kernel_launch(void* const* d_in, const int* in_sizes, int n_in,
                              void* d_out, int out_size) {
    const float* x       = (const float*)d_in[0];
    const float* conv0_w = (const float*)d_in[1];
    const float* bn0_g   = (const float*)d_in[2];
    const float* bn0_b   = (const float*)d_in[3];
    const float* bn0_m   = (const float*)d_in[4];
    const float* bn0_v   = (const float*)d_in[5];
    const float* convs_w = (const float*)d_in[6];
    const float* bns_g   = (const float*)d_in[7];
    const float* bns_b   = (const float*)d_in[8];
    const float* bns_m   = (const float*)d_in[9];
    const float* bns_v   = (const float*)d_in[10];
    const float* plif_w  = (const float*)d_in[11];
    const float* ft_w    = (const float*)d_in[12];
    const float* ft_b    = (const float*)d_in[13];
    const float* gat_W   = (const float*)d_in[14];
    const float* gat_a   = (const float*)d_in[15];
    const float* out_w   = (const float*)d_in[16];
    float* dout = (float*)d_out;

    const int k1_smem = 3 * 66 * 66 * (int)sizeof(float);       // 52272 B
    const int i2c_smem = 128 * 102 * (int)sizeof(float);        // 52224 B
    cudaFuncSetAttribute(k1_conv0, cudaFuncAttributeMaxDynamicSharedMemorySize, k1_smem);
    cudaFuncSetAttribute(k_im2col, cudaFuncAttributeMaxDynamicSharedMemorySize, i2c_smem);
    cudaFuncSetAttribute(k3m_nodeconv, cudaFuncAttributeMaxDynamicSharedMemorySize, SMEMT);

    k0_zero<<<2048, 256>>>();
    k_wsplit<<<(5 * COUT * KK + 255) / 256, 256>>>(convs_w);
    k_wtrans<<<64, 256>>>(ft_w, gat_W);
    for (int t = 0; t < TT; t++) {
        k1_conv0<<<dim3(BB, COUT), 256, k1_smem>>>(x, conv0_w, bn0_g, bn0_b, bn0_m, bn0_v,
                                                   plif_w, out_w, dout, t);
        k2_graph<<<BB, 128>>>(ft_b, gat_a);
        k_im2col<<<dim3(BB, 32), 256, i2c_smem>>>();
        k3m_nodeconv<<<128, 256, SMEMT>>>(bns_g, bns_b, bns_m, bns_v,
                                          plif_w, out_w, dout, t);
        k5_feats<<<BB, 128>>>(ft_b);
    }
}

// round 16
// speedup vs baseline: 2.2775x; 1.4081x over previous
#include <cuda_runtime.h>
#include <cuda_fp16.h>
#include <cuda_bf16.h>
#include <cstddef>
#include <cstdint>

// Problem constants
#define TT 4
#define BB 16
#define CIN 3
#define HIMG 64
#define WIMG 64
#define NN 6
#define COUT 128
#define HP 32
#define WP 32
#define KK 1152          // 128 ic * 9 taps (kk = ic*9 + ky*3 + kx)

// Persistent state
__device__ float g_v0[BB * COUT * HIMG * WIMG];
__device__ float g_vn[5 * BB * COUT * HP * WP];   // [i][b][co][px]
__device__ float g_traces[BB * NN * COUT];
__device__ float g_out0[BB * COUT * HP * WP];
__device__ float g_mean0[BB * COUT];
__device__ float g_feat0[BB * COUT];
__device__ float g_msp[5 * BB * COUT];            // raw spike sums (k5 /1024)
__device__ float g_c[BB * NN];

// Tensor-path scratch
__device__ __half g_X[(size_t)BB * 1024 * KK];    // [b][px][kk]
__device__ __half g_W[2 * 5 * COUT * KK];         // [split][i][co][kk] fp16 2-split
__device__ float g_ftwT[COUT * COUT];             // ftw transposed [d][co]
__device__ float g_gatWT[COUT * COUT];            // gatW transposed [k][co]

__device__ __forceinline__ float sigf(float x) { return 1.f / (1.f + expf(-x)); }

__device__ __forceinline__ uint32_t smem_u32(const void* p) {
    uint32_t a;
    asm("{ .reg .u64 t; cvta.to.shared.u64 t, %1; cvt.u32.u64 %0, t; }" : "=r"(a) : "l"(p));
    return a;
}
__device__ __forceinline__ void ldm4(uint32_t* r, uint32_t addr) {
    asm volatile("ldmatrix.sync.aligned.m8n8.x4.shared.b16 {%0,%1,%2,%3}, [%4];"
                 : "=r"(r[0]), "=r"(r[1]), "=r"(r[2]), "=r"(r[3]) : "r"(addr));
}
__device__ __forceinline__ void mma16816(float* c, const uint32_t* a,
                                         uint32_t b0, uint32_t b1) {
    asm volatile("mma.sync.aligned.m16n8k16.row.col.f32.f16.f16.f32 "
                 "{%0,%1,%2,%3}, {%4,%5,%6,%7}, {%8,%9}, {%0,%1,%2,%3};"
                 : "+f"(c[0]), "+f"(c[1]), "+f"(c[2]), "+f"(c[3])
                 : "r"(a[0]), "r"(a[1]), "r"(a[2]), "r"(a[3]), "r"(b0), "r"(b1));
}
__device__ __forceinline__ void cpa16(uint32_t d, const void* g) {
    asm volatile("cp.async.cg.shared.global [%0], [%1], 16;" :: "r"(d), "l"(g));
}
#define CPA_COMMIT() asm volatile("cp.async.commit_group;" ::: "memory")
#define CPA_WAIT1()  asm volatile("cp.async.wait_group 1;" ::: "memory")

// ---------------------------------------------------------------------------
// K0: zero state
// ---------------------------------------------------------------------------
__global__ void k0_zero() {
    const size_t n0 = (size_t)BB * COUT * HIMG * WIMG;
    const size_t n1 = (size_t)5 * BB * COUT * HP * WP;
    const size_t n2 = (size_t)BB * NN * COUT;
    const size_t tot = n0 + n1 + n2;
    for (size_t i = (size_t)blockIdx.x * blockDim.x + threadIdx.x; i < tot;
         i += (size_t)gridDim.x * blockDim.x) {
        if (i < n0) g_v0[i] = 0.f;
        else if (i < n0 + n1) g_vn[i - n0] = 0.f;
        else g_traces[i - n0 - n1] = 0.f;
    }
}

// ---------------------------------------------------------------------------
// K_wsplit: 2-way fp16 split of node-conv weights (residual <= ~2^-22 |w|)
// ---------------------------------------------------------------------------
__global__ void k_wsplit(const float* __restrict__ convw) {
    int gid = blockIdx.x * 256 + threadIdx.x;    // 5*128*1152 = 737280
    if (gid >= 5 * COUT * KK) return;
    float w = convw[gid];
    __half h = __float2half_rn(w);
    float r1 = w - __half2float(h);
    __half l = __float2half_rn(r1);
    g_W[gid] = h;
    g_W[5 * COUT * KK + gid] = l;
}

// ---------------------------------------------------------------------------
// K_wtrans: transpose ft_w and gat_W once for coalesced matvec access
// ---------------------------------------------------------------------------
__global__ void k_wtrans(const float* __restrict__ ftw, const float* __restrict__ gatW) {
    int i = blockIdx.x * 256 + threadIdx.x;
    if (i < COUT * COUT) {
        int r = i >> 7, c = i & 127;
        g_ftwT[c * COUT + r] = ftw[i];
        g_gatWT[c * COUT + r] = gatW[i];
    }
}

// ---------------------------------------------------------------------------
// K_im2col: g_X[b][px][kk] = out0[b][ic][y+ky-1][x+kx-1] (fp16, exact)
// grid (16 b, 32 y), 256 threads, dyn smem = 128*102 floats
// ---------------------------------------------------------------------------
__global__ void k_im2col() {
    extern __shared__ float in_s[];   // [128 ic][3 rows][34 x]
    int b = blockIdx.x, y = blockIdx.y, tid = threadIdx.x;
    for (int idx = tid; idx < 128 * 102; idx += 256) {
        int ic = idx / 102, rem = idx % 102, row = rem / 34, xx = rem % 34;
        int yy = y + row - 1, xg = xx - 1;
        float v = 0.f;
        if ((unsigned)yy < 32u && (unsigned)xg < 32u)
            v = g_out0[((size_t)b * COUT + ic) * 1024 + yy * 32 + xg];
        in_s[idx] = v;
    }
    __syncthreads();
    __half* dst = g_X + ((size_t)b * 1024 + y * 32) * KK;
    for (int q = tid; q < 32 * 144; q += 256) {
        int x = q / 144, kg = q % 144;
        __half tmp[8];
        #pragma unroll
        for (int j = 0; j < 8; j++) {
            int kk = kg * 8 + j;
            int ic = kk / 9, tap = kk - ic * 9;
            int ky = tap / 3, kx = tap - ky * 3;
            tmp[j] = __float2half_rn(in_s[ic * 102 + ky * 34 + x + kx]);
        }
        *(uint4*)(dst + (size_t)x * KK + kg * 8) = *(const uint4*)tmp;
    }
}

// ---------------------------------------------------------------------------
// K1: conv0(3->128, 3x3, SAME) + BN + PLIF + spike + 2x2 avgpool (scalar)
// ---------------------------------------------------------------------------
__global__ void k1_conv0(const float* __restrict__ x, const float* __restrict__ w0,
                         const float* __restrict__ bg, const float* __restrict__ bb,
                         const float* __restrict__ bm, const float* __restrict__ bv,
                         const float* __restrict__ plw, const float* __restrict__ outw,
                         float* __restrict__ dout, int t) {
    extern __shared__ float tile[];   // [3][66][66]
    __shared__ float ws[27];
    __shared__ float red[256];
    int b = blockIdx.x, c = blockIdx.y, tid = threadIdx.x;

    const float* xb = x + (((size_t)t * BB + b) * CIN) * (HIMG * WIMG);
    for (int idx = tid; idx < 3 * 66 * 66; idx += 256) {
        int ic = idx / 4356, rem = idx % 4356;
        int r = rem / 66, cc = rem % 66;
        int y = r - 1, xx = cc - 1;
        float v = 0.f;
        if ((unsigned)y < 64u && (unsigned)xx < 64u) v = xb[ic * 4096 + y * 64 + xx];
        tile[idx] = v;
    }
    if (tid < 27) ws[tid] = w0[c * 27 + tid];
    __syncthreads();

    float scale = bg[c] / sqrtf(bv[c] + 1e-5f);
    float shift = bb[c] - bm[c] * scale;
    float sg = sigf(plw[0]);
    float wsig0 = sigf(outw[0]);

    float* v0p = g_v0 + ((size_t)b * COUT + c) * (HIMG * WIMG);
    float* o0p = g_out0 + ((size_t)b * COUT + c) * (HP * WP);
    float* dop = dout + ((((size_t)t * BB + b) * COUT + c)) * (HP * WP);

    float lsum = 0.f;
    for (int k = 0; k < 4; k++) {
        int q = tid + k * 256;
        int ph = q >> 5, pw = q & 31;
        float psum = 0.f;
        #pragma unroll
        for (int dy = 0; dy < 2; dy++) {
            #pragma unroll
            for (int dx = 0; dx < 2; dx++) {
                int yy = 2 * ph + dy, xx = 2 * pw + dx;
                float acc = 0.f;
                #pragma unroll
                for (int ic = 0; ic < 3; ic++) {
                    const float* tp = tile + ic * 4356 + yy * 66 + xx;
                    const float* wp = ws + ic * 9;
                    #pragma unroll
                    for (int ky = 0; ky < 3; ky++)
                        #pragma unroll
                        for (int kx = 0; kx < 3; kx++)
                            acc += tp[ky * 66 + kx] * wp[ky * 3 + kx];
                }
                float bnv = acc * scale + shift;
                float vold = v0p[yy * 64 + xx];
                float v = vold + (bnv - vold) * sg;
                float sp = (v >= 1.f) ? 1.f : 0.f;
                v0p[yy * 64 + xx] = (v >= 1.f) ? 0.f : v;
                psum += sp;
            }
        }
        float o = psum * 0.25f;
        o0p[q] = o;
        dop[q] = wsig0 * o;
        lsum += o;
    }
    red[tid] = lsum;
    __syncthreads();
    for (int off = 128; off; off >>= 1) {
        if (tid < off) red[tid] += red[tid + off];
        __syncthreads();
    }
    if (tid == 0) g_mean0[b * COUT + c] = red[0] * (1.f / 1024.f);
}

// ---------------------------------------------------------------------------
// K2: per-batch tiny graph work (+ zero g_msp). Coalesced matvecs via g_*T.
// ---------------------------------------------------------------------------
__global__ void k2_graph(const float* __restrict__ ftb, const float* __restrict__ gata) {
    int b = blockIdx.x, tid = threadIdx.x;
    __shared__ float tr[NN * COUT];
    __shared__ float m0[COUT];
    __shared__ float hp[NN * COUT];
    __shared__ float e1[NN * 4], e2[NN * 4];
    __shared__ float attn[36], Sm[36], adj[36], opm[36], dis[NN];

    for (int i = 0; i < 5; i++) g_msp[((size_t)i * BB + b) * COUT + tid] = 0.f;

    m0[tid] = g_mean0[b * COUT + tid];
    for (int n = 0; n < NN; n++) tr[n * COUT + tid] = g_traces[((size_t)b * NN + n) * COUT + tid];
    __syncthreads();

    // feat0 = relu(mean0 @ ft_w^T + ft_b)  -- coalesced via ftwT
    float f = ftb[tid];
    #pragma unroll 8
    for (int d = 0; d < COUT; d++) f += m0[d] * g_ftwT[d * COUT + tid];
    f = fmaxf(f, 0.f);
    g_feat0[b * COUT + tid] = f;
    float t0 = 0.6f * tr[tid] + 0.4f * f;
    tr[tid] = t0;
    g_traces[(size_t)b * NN * COUT + tid] = t0;
    __syncthreads();

    // hp[n][tid] = sum_k tr[n][k] * gatW[tid][k]  -- coalesced via gatWT, 6-way ILP
    {
        float s[NN];
        #pragma unroll
        for (int n = 0; n < NN; n++) s[n] = 0.f;
        #pragma unroll 4
        for (int k = 0; k < COUT; k++) {
            float w = g_gatWT[k * COUT + tid];
            #pragma unroll
            for (int n = 0; n < NN; n++) s[n] += tr[n * COUT + k] * w;
        }
        #pragma unroll
        for (int n = 0; n < NN; n++) hp[n * COUT + tid] = s[n];
    }
    __syncthreads();

    if (tid < NN * 4) {
        int n = tid >> 2, h = tid & 3;
        float s1 = 0.f, s2 = 0.f;
        for (int d = 0; d < 32; d++) {
            float hv = hp[n * COUT + h * 32 + d];
            s1 += hv * gata[h * 64 + d];
            s2 += hv * gata[h * 64 + 32 + d];
        }
        e1[tid] = s1;
        e2[tid] = s2;
    }
    __syncthreads();

    if (tid < 36) {
        int i = tid / 6, j = tid % 6;
        float s = 0.f;
        for (int h = 0; h < 4; h++) {
            float x1 = e1[i * 4 + h] + e2[j * 4 + h];
            float x2 = e1[j * 4 + h] + e2[i * 4 + h];
            x1 = x1 > 0.f ? x1 : 0.2f * x1;
            x2 = x2 > 0.f ? x2 : 0.2f * x2;
            s += 0.5f * (x1 + x2);
        }
        attn[tid] = s * 0.25f;
    }
    __syncthreads();

    if (tid < NN) {
        int i = tid;
        float mx = -1e30f;
        for (int j = 0; j < 6; j++) mx = fmaxf(mx, attn[i * 6 + j] * 100.f);
        float ex[6], sum = 0.f;
        for (int j = 0; j < 6; j++) { ex[j] = expf(attn[i * 6 + j] * 100.f - mx); sum += ex[j]; }
        for (int j = 0; j < 6; j++) Sm[i * 6 + j] = ex[j] / sum;
    }
    __syncthreads();

    if (tid < NN) {
        int i = tid;
        float a[6];
        for (int j = 0; j < 6; j++) a[j] = Sm[i * 6 + j];
        float kth = 0.f;
        for (int r = 0; r < 3; r++) {
            int bi = 0; float bvv = -1e30f;
            for (int j = 0; j < 6; j++) if (a[j] > bvv) { bvv = a[j]; bi = j; }
            kth = bvv; a[bi] = -1e30f;
        }
        for (int j = 0; j < 6; j++) Sm[i * 6 + j] = (Sm[i * 6 + j] >= kth) ? Sm[i * 6 + j] : 0.f;
    }
    __syncthreads();

    if (tid < 36) { int i = tid / 6, j = tid % 6; adj[tid] = 0.5f * (Sm[i * 6 + j] + Sm[j * 6 + i]); }
    __syncthreads();
    if (tid < NN) {
        float s = 0.f;
        for (int j = 0; j < 6; j++) s += adj[tid * 6 + j];
        dis[tid] = 1.f / sqrtf(s + 1e-6f);
    }
    __syncthreads();
    if (tid < 36) { int i = tid / 6, j = tid % 6; opm[tid] = dis[i] * adj[tid] * dis[j]; }
    __syncthreads();
    if (tid < NN) {
        float s = 0.f;
        for (int j = 0; j < 6; j++) s += opm[tid * 6 + j] * opm[j * 6 + 0];
        g_c[b * NN + tid] = s;
    }
}

// ---------------------------------------------------------------------------
// K3M: warp-MMA node conv, fp16 2-split, cp.async double-buffered pipeline.
// Per CTA: D[128 px][128 co]; 8 warps (2M x 4N); K chunks of 64.
// 90 flattened (node, chunk) iterations; prefetch it+1 while computing it.
// ---------------------------------------------------------------------------
#define BUFB   55296                 // per buffer: X 18432 + 2 W splits * 18432
#define WOFF   18432
#define WSZ    18432
#define D_OFF  110592                // D tile after both buffers
#define SS_OFF 179200                // 110592 + 128*134*4
#define CS_OFF 179712
#define SH_OFF 180224
#define SMEMT  180736
#define DSTRIDE 134

__device__ __forceinline__ void k3_stage(char* smem, int buf, int tid, int node, int c,
                                         const __half* xsrc) {
    char* base = smem + buf * BUFB;
    #pragma unroll
    for (int rep = 0; rep < 4; rep++) {
        int idx = rep * 256 + tid;
        int px = idx >> 3, seg = idx & 7;
        cpa16(smem_u32(base + (px * 72 + seg * 8) * 2),
              xsrc + (size_t)px * KK + c * 64 + seg * 8);
    }
    #pragma unroll
    for (int rep = 0; rep < 8; rep++) {
        int idx = rep * 256 + tid;
        int s = idx >> 10, r = idx & 1023;
        int co = r >> 3, seg = r & 7;
        cpa16(smem_u32(base + WOFF + s * WSZ + (co * 72 + seg * 8) * 2),
              g_W + ((((size_t)s * 5 + node) * COUT + co) * KK) + c * 64 + seg * 8);
    }
}

__global__ void __launch_bounds__(256) k3m_nodeconv(
    const float* __restrict__ bg, const float* __restrict__ bb,
    const float* __restrict__ bm, const float* __restrict__ bv,
    const float* __restrict__ plw, const float* __restrict__ outw,
    float* __restrict__ dout, int t) {
    extern __shared__ char smem[];
    int tid = threadIdx.x;
    int wid = tid >> 5, lane = tid & 31;
    int wm = wid >> 2, wn = wid & 3;
    int b = blockIdx.x >> 3, pxt = blockIdx.x & 7;
    int pxbase = pxt * 128;

    const __half* xsrc = g_X + ((size_t)b * 1024 + pxbase) * KK;
    float* Dsm = (float*)(smem + D_OFF);
    float* ssm = (float*)(smem + SS_OFF);
    float* csm = (float*)(smem + CS_OFF);
    float* shm = (float*)(smem + SH_OFF);
    int gp = lane >> 2, tg = lane & 3;
    uint32_t lrow_off = (uint32_t)(((lane & 15) * 72 + (lane >> 4) * 8) * 2);

    float acc[4][4][4];

    k3_stage(smem, 0, tid, 0, 0, xsrc);
    CPA_COMMIT();

    for (int it = 0; it < 90; it++) {
        int node = it / 18, c = it % 18;
        if (it + 1 < 90)
            k3_stage(smem, (it + 1) & 1, tid, (it + 1) / 18, (it + 1) % 18, xsrc);
        CPA_COMMIT();
        CPA_WAIT1();
        __syncthreads();

        if (c == 0) {
            #pragma unroll
            for (int mt = 0; mt < 4; mt++)
                #pragma unroll
                for (int nt = 0; nt < 4; nt++)
                    #pragma unroll
                    for (int u = 0; u < 4; u++) acc[mt][nt][u] = 0.f;
        }

        char* base = smem + (it & 1) * BUFB;
        uint32_t sxa = smem_u32(base) + (uint32_t)(wm * 64 * 72 * 2) + lrow_off;
        uint32_t sba = smem_u32(base + WOFF) + (uint32_t)(wn * 32 * 72 * 2) + lrow_off;

        #pragma unroll
        for (int ks = 0; ks < 4; ks++) {
            uint32_t afr[4][4];
            #pragma unroll
            for (int mt = 0; mt < 4; mt++)
                ldm4(afr[mt], sxa + (uint32_t)((mt * 16 * 72 + ks * 16) * 2));
            #pragma unroll
            for (int s = 0; s < 2; s++) {
                #pragma unroll
                for (int ntg = 0; ntg < 2; ntg++) {
                    uint32_t bfr[4];
                    ldm4(bfr, sba + (uint32_t)(s * WSZ) +
                              (uint32_t)((ntg * 16 * 72 + ks * 16) * 2));
                    #pragma unroll
                    for (int mt = 0; mt < 4; mt++) {
                        mma16816(acc[mt][ntg * 2 + 0], afr[mt], bfr[0], bfr[2]);
                        mma16816(acc[mt][ntg * 2 + 1], afr[mt], bfr[1], bfr[3]);
                    }
                }
            }
        }

        if (c == 17) {
            // ---- node epilogue (D region is disjoint from prefetch buffers) ----
            float ci = g_c[b * NN + node + 1];
            float sg = sigf(plw[node + 1]);
            float wsg = sigf(outw[node + 1]);
            if (tid < 128) {
                float sc = bg[node * COUT + tid] / sqrtf(bv[node * COUT + tid] + 1e-5f);
                csm[tid] = ci * sc;
                shm[tid] = bb[node * COUT + tid] - bm[node * COUT + tid] * sc;
                ssm[tid] = 0.f;
            }
            #pragma unroll
            for (int mt = 0; mt < 4; mt++) {
                #pragma unroll
                for (int nt = 0; nt < 4; nt++) {
                    int px0 = wm * 64 + mt * 16 + gp;
                    int co0 = wn * 32 + nt * 8 + tg * 2;
                    *(float2*)&Dsm[px0 * DSTRIDE + co0] =
                        make_float2(acc[mt][nt][0], acc[mt][nt][1]);
                    *(float2*)&Dsm[(px0 + 8) * DSTRIDE + co0] =
                        make_float2(acc[mt][nt][2], acc[mt][nt][3]);
                }
            }
            __syncthreads();

            float* vn0 = g_vn + (((size_t)node * BB + b) * COUT) * 1024 + pxbase;
            float* do0 = dout + (((size_t)t * BB + b) * COUT) * 1024 + pxbase;
            #pragma unroll 4
            for (int rep = 0; rep < 64; rep++) {
                int idxq = rep * 256 + tid;
                int co = idxq >> 7, px = idxq & 127;
                float val = Dsm[px * DSTRIDE + co];
                float y = val * csm[co] + shm[co];
                float* vp = vn0 + (size_t)co * 1024 + px;
                float vold = *vp;
                float v = vold + (y - vold) * sg;
                float sp = (v >= 1.f) ? 1.f : 0.f;
                *vp = (v >= 1.f) ? 0.f : v;
                do0[(size_t)co * 1024 + px] += wsg * sp;
                float rr = sp;
                #pragma unroll
                for (int o = 16; o; o >>= 1) rr += __shfl_xor_sync(0xffffffffu, rr, o);
                if (lane == 0) atomicAdd(&ssm[co], rr);
            }
            __syncthreads();
            if (tid < 128)
                atomicAdd(&g_msp[((size_t)node * BB + b) * COUT + tid], ssm[tid]);
        }
        __syncthreads();
    }
}

// ---------------------------------------------------------------------------
// K5: feats_i = relu(spike_sum/1024 @ ft_w^T + ft_b); trace update (coalesced)
// ---------------------------------------------------------------------------
__global__ void k5_feats(const float* __restrict__ ftb) {
    int b = blockIdx.x, tid = threadIdx.x;
    __shared__ float ms[5 * COUT];
    for (int i = 0; i < 5; i++)
        ms[i * COUT + tid] = g_msp[((size_t)i * BB + b) * COUT + tid] * (1.f / 1024.f);
    __syncthreads();
    float feats[6];
    feats[0] = g_feat0[b * COUT + tid];
    {
        float s[5];
        #pragma unroll
        for (int i = 0; i < 5; i++) s[i] = ftb[tid];
        #pragma unroll 4
        for (int d = 0; d < COUT; d++) {
            float w = g_ftwT[d * COUT + tid];
            #pragma unroll
            for (int i = 0; i < 5; i++) s[i] += ms[i * COUT + d] * w;
        }
        #pragma unroll
        for (int i = 0; i < 5; i++) feats[i + 1] = fmaxf(s[i], 0.f);
    }
    for (int n = 0; n < NN; n++) {
        size_t ix = ((size_t)b * NN + n) * COUT + tid;
        g_traces[ix] = 0.6f * g_traces[ix] + 0.4f * feats[n];
    }
}

// ---------------------------------------------------------------------------
extern "C" void kernel_launch(void* const* d_in, const int* in_sizes, int n_in,
                              void* d_out, int out_size) {
    const float* x       = (const float*)d_in[0];
    const float* conv0_w = (const float*)d_in[1];
    const float* bn0_g   = (const float*)d_in[2];
    const float* bn0_b   = (const float*)d_in[3];
    const float* bn0_m   = (const float*)d_in[4];
    const float* bn0_v   = (const float*)d_in[5];
    const float* convs_w = (const float*)d_in[6];
    const float* bns_g   = (const float*)d_in[7];
    const float* bns_b   = (const float*)d_in[8];
    const float* bns_m   = (const float*)d_in[9];
    const float* bns_v   = (const float*)d_in[10];
    const float* plif_w  = (const float*)d_in[11];
    const float* ft_w    = (const float*)d_in[12];
    const float* ft_b    = (const float*)d_in[13];
    const float* gat_W   = (const float*)d_in[14];
    const float* gat_a   = (const float*)d_in[15];
    const float* out_w   = (const float*)d_in[16];
    float* dout = (float*)d_out;

    const int k1_smem = 3 * 66 * 66 * (int)sizeof(float);       // 52272 B
    const int i2c_smem = 128 * 102 * (int)sizeof(float);        // 52224 B
    cudaFuncSetAttribute(k1_conv0, cudaFuncAttributeMaxDynamicSharedMemorySize, k1_smem);
    cudaFuncSetAttribute(k_im2col, cudaFuncAttributeMaxDynamicSharedMemorySize, i2c_smem);
    cudaFuncSetAttribute(k3m_nodeconv, cudaFuncAttributeMaxDynamicSharedMemorySize, SMEMT);

    k0_zero<<<2048, 256>>>();
    k_wsplit<<<(5 * COUT * KK + 255) / 256, 256>>>(convs_w);
    k_wtrans<<<64, 256>>>(ft_w, gat_W);
    for (int t = 0; t < TT; t++) {
        k1_conv0<<<dim3(BB, COUT), 256, k1_smem>>>(x, conv0_w, bn0_g, bn0_b, bn0_m, bn0_v,
                                                   plif_w, out_w, dout, t);
        k2_graph<<<BB, 128>>>(ft_b, gat_a);
        k_im2col<<<dim3(BB, 32), 256, i2c_smem>>>();
        k3m_nodeconv<<<128, 256, SMEMT>>>(bns_g, bns_b, bns_m, bns_v,
                                          plif_w, out_w, dout, t);
        k5_feats<<<BB, 128>>>(ft_b);
    }
}